// round 12
// baseline (speedup 1.0000x reference)
#include <cuda_runtime.h>
#include <cuda_fp16.h>
#include <cstdint>

#define D_DIM 1024
#define H_DIM 2048
#define E_NUM 8
#define T_MAX 4096
#define BM 128
#define MAX_TILES 72
#define MAX_ROWS  (MAX_TILES * BM)

#define BKW 64
#define UP_NK 16
#define DN_NK 32
#define STAGE_BYTES 49152
#define NSTAGE 4
#define GEMM_SMEM (NSTAGE * STAGE_BYTES + 1024)

// ---------------- device-global scratch ------------------------------------
__device__ int   g_counts[E_NUM];
__device__ int   g_tile_expert[MAX_TILES];
__device__ int   g_list[E_NUM * T_MAX];
__device__ float g_probs[2 * T_MAX];
__device__ int   g_gather[MAX_ROWS];
__device__ int   g_row_of[2 * T_MAX];
__device__ __half g_xH [(size_t)T_MAX * D_DIM];
__device__ __half g_w1H[(size_t)E_NUM * H_DIM * D_DIM];
__device__ __half g_w2H[(size_t)E_NUM * H_DIM * D_DIM];
__device__ __half g_w3H[(size_t)E_NUM * D_DIM * H_DIM];
__device__ __half g_hH [(size_t)MAX_ROWS * H_DIM];
__device__ float g_y[(size_t)MAX_ROWS * D_DIM];

// ---------------- side stream for conv overlap (load-time init) -------------
static cudaStream_t g_s1 = 0;
static cudaEvent_t  g_ef = 0, g_ej = 0;
namespace {
struct SideInit {
    SideInit() {
        if (cudaStreamCreateWithFlags(&g_s1, cudaStreamNonBlocking) != cudaSuccess) g_s1 = 0;
        if (cudaEventCreateWithFlags(&g_ef, cudaEventDisableTiming) != cudaSuccess) g_ef = 0;
        if (cudaEventCreateWithFlags(&g_ej, cudaEventDisableTiming) != cudaSuccess) g_ej = 0;
    }
};
SideInit s_side_init;
}

// ---------------- helpers ----------------------------------------------------
__device__ __forceinline__ uint32_t smem_u32(const void* p) {
    uint32_t a;
    asm("{ .reg .u64 t; cvta.to.shared.u64 t, %1; cvt.u32.u64 %0, t; }"
        : "=r"(a) : "l"(p));
    return a;
}
__device__ __forceinline__ void ldsm4(uint32_t& r0, uint32_t& r1, uint32_t& r2,
                                      uint32_t& r3, uint32_t addr) {
    asm volatile("ldmatrix.sync.aligned.m8n8.x4.shared.b16 {%0,%1,%2,%3}, [%4];"
                 : "=r"(r0), "=r"(r1), "=r"(r2), "=r"(r3) : "r"(addr));
}
__device__ __forceinline__ void mma16816(float* c, const uint32_t* a,
                                         const uint32_t* b) {
    asm volatile(
        "mma.sync.aligned.m16n8k16.row.col.f32.f16.f16.f32 "
        "{%0,%1,%2,%3},{%4,%5,%6,%7},{%8,%9},{%0,%1,%2,%3};"
        : "+f"(c[0]), "+f"(c[1]), "+f"(c[2]), "+f"(c[3])
        : "r"(a[0]), "r"(a[1]), "r"(a[2]), "r"(a[3]), "r"(b[0]), "r"(b[1]));
}
__device__ __forceinline__ void cp16(uint32_t dst, const void* src, int srcsize) {
    asm volatile("cp.async.cg.shared.global [%0], [%1], 16, %2;"
                 :: "r"(dst), "l"(src), "r"(srcsize) : "memory");
}
#define CP_COMMIT asm volatile("cp.async.commit_group;" ::: "memory")
template <int N>
__device__ __forceinline__ void cp_wait() {
    asm volatile("cp.async.wait_group %0;" :: "n"(N) : "memory");
}
__device__ __forceinline__ float silu_f(float v) { return v / (1.0f + __expf(-v)); }
__device__ __forceinline__ int sw_off(int r, int c) {
    return r * 128 + ((c ^ (r & 7)) << 4);
}

// ---------------- K0: init ----------------------------------------------------
__global__ void init_kernel() {
    if (threadIdx.x < E_NUM) g_counts[threadIdx.x] = 0;
}

// ---------------- K1: router (fused x->fp16) -----------------------------------
__global__ void router_kernel(const float* __restrict__ x,
                              const float* __restrict__ gw, int T) {
    int warp = blockIdx.x * (blockDim.x >> 5) + (threadIdx.x >> 5);
    int lane = threadIdx.x & 31;
    if (warp >= T) return;
    const float* xr = x + (size_t)warp * D_DIM;
    __half* xh = g_xH + (size_t)warp * D_DIM;

    float acc[E_NUM];
#pragma unroll
    for (int e = 0; e < E_NUM; e++) acc[e] = 0.0f;
#pragma unroll
    for (int i = 0; i < D_DIM / 128; i++) {
        int d = i * 128 + lane * 4;
        float4 xv = *(const float4*)(xr + d);
        __half2 h0 = __floats2half2_rn(xv.x, xv.y);
        __half2 h1 = __floats2half2_rn(xv.z, xv.w);
        *(uint2*)(xh + d) = make_uint2(*(uint32_t*)&h0, *(uint32_t*)&h1);
#pragma unroll
        for (int e = 0; e < E_NUM; e++) {
            float4 gv = *(const float4*)(gw + e * D_DIM + d);
            acc[e] += xv.x * gv.x + xv.y * gv.y + xv.z * gv.z + xv.w * gv.w;
        }
    }
#pragma unroll
    for (int e = 0; e < E_NUM; e++) {
#pragma unroll
        for (int off = 16; off > 0; off >>= 1)
            acc[e] += __shfl_xor_sync(0xFFFFFFFFu, acc[e], off);
    }
    if (lane == 0) {
        int e0 = 0; float s0 = acc[0];
#pragma unroll
        for (int e = 1; e < E_NUM; e++) if (acc[e] > s0) { s0 = acc[e]; e0 = e; }
        int e1 = -1; float s1 = -3.4e38f;
#pragma unroll
        for (int e = 0; e < E_NUM; e++)
            if (e != e0 && acc[e] > s1) { s1 = acc[e]; e1 = e; }
        float x1 = __expf(s1 - s0);
        float inv = 1.0f / (1.0f + x1);
        int t = warp;
        g_probs[2 * t] = inv;
        g_probs[2 * t + 1] = x1 * inv;
        int j0 = atomicAdd(&g_counts[e0], 1);
        g_list[e0 * T_MAX + j0] = (t << 1);
        int j1 = atomicAdd(&g_counts[e1], 1);
        g_list[e1 * T_MAX + j1] = (t << 1) | 1;
    }
}

// ---------------- K2: build (inline scan) --------------------------------------
__global__ void build_kernel() {
    __shared__ int s_exp, s_off, s_cnt;
    if (threadIdx.x == 0) {
        int off = 0, nt = 0, my_e = -1, my_off = 0, my_cnt = 0;
#pragma unroll
        for (int e = 0; e < E_NUM; e++) {
            int c = g_counts[e];
            int te = (c + BM - 1) / BM;
            if ((int)blockIdx.x >= nt && (int)blockIdx.x < nt + te) {
                my_e = e; my_off = off; my_cnt = c;
            }
            nt += te;
            off += te * BM;
        }
        g_tile_expert[blockIdx.x] = my_e;
        s_exp = my_e; s_off = my_off; s_cnt = my_cnt;
    }
    __syncthreads();
    int e = s_exp;
    int r = blockIdx.x * BM + threadIdx.x;
    if (e < 0) { g_gather[r] = -1; return; }
    int j = r - s_off;
    if (j < s_cnt) {
        int entry = g_list[e * T_MAX + j];
        g_gather[r] = entry >> 1;
        g_row_of[entry] = r;
    } else {
        g_gather[r] = -1;
    }
}

// ---------------- weight conversion (side stream) ------------------------------
__global__ void conv_w_all_kernel(const float* __restrict__ w1,
                                  const float* __restrict__ w2,
                                  const float* __restrict__ w3, long n4) {
    long i = blockIdx.x * (long)blockDim.x + threadIdx.x;
    if (i >= 3 * n4) return;
    const float* src;
    __half* dst;
    long j;
    if (i < n4)           { src = w1; dst = g_w1H; j = i; }
    else if (i < 2 * n4)  { src = w2; dst = g_w2H; j = i - n4; }
    else                  { src = w3; dst = g_w3H; j = i - 2 * n4; }
    long eb = j * 4;
    float4 v = *(const float4*)(src + eb);
    __half2 h0 = __floats2half2_rn(v.x, v.y);
    __half2 h1 = __floats2half2_rn(v.z, v.w);
    *(uint2*)(dst + eb) = make_uint2(*(uint32_t*)&h0, *(uint32_t*)&h1);
}

// ---------------- K4: up GEMM — 512 thr, 16 warps, warp 32x32, A+B preload -----
__global__ void __launch_bounds__(512, 1) gemm_up_mma() {
    const int e = g_tile_expert[blockIdx.y];
    if (e < 0) return;
    extern __shared__ char raw[];
    char* dsm = (char*)(((uintptr_t)raw + 1023) & ~(uintptr_t)1023);
    __shared__ int sg[BM];
    const int tid = threadIdx.x;
    const int m0 = blockIdx.y * BM;
    const int bn0 = blockIdx.x * 128;
    if (tid < BM) sg[tid] = g_gather[m0 + tid];
    __syncthreads();
    const uint32_t sb = smem_u32(dsm);
    const int lane = tid & 31, wid = tid >> 5;
    const int wm = wid & 3, wn = wid >> 2;

    const char* asrc[2]; int asz[2]; int dA[2];
    const char* b1s[2];
    const size_t w2delta = (const char*)g_w2H - (const char*)g_w1H;
#pragma unroll
    for (int i = 0; i < 2; i++) {
        int idx = tid + i * 512;
        int r = idx >> 3, c = idx & 7;
        dA[i] = sw_off(r, c);
        int tok = sg[r];
        asrc[i] = (tok >= 0) ? (const char*)(g_xH + (size_t)tok * D_DIM + c * 8)
                             : (const char*)g_xH;
        asz[i] = (tok >= 0) ? 16 : 0;
        b1s[i] = (const char*)(g_w1H + ((size_t)e * H_DIM + bn0 + r) * D_DIM + c * 8);
    }

#define U_LOAD(KT) do {                                                         \
    const int _s = (KT) % NSTAGE;                                               \
    const uint32_t _b = sb + _s * STAGE_BYTES;                                  \
    const int _k = (KT) * (BKW * 2);                                            \
    _Pragma("unroll") for (int i = 0; i < 2; i++) {                             \
        cp16(_b + dA[i], asrc[i] + _k, asz[i]);                                 \
        cp16(_b + 16384 + dA[i], b1s[i] + _k, 16);                              \
        cp16(_b + 32768 + dA[i], b1s[i] + w2delta + _k, 16);                    \
    } } while (0)

    U_LOAD(0); CP_COMMIT;
    U_LOAD(1); CP_COMMIT;
    U_LOAD(2); CP_COMMIT;

    float cu[2][4][4], cv[2][4][4];
#pragma unroll
    for (int a = 0; a < 2; a++)
#pragma unroll
        for (int b = 0; b < 4; b++)
#pragma unroll
            for (int c = 0; c < 4; c++) { cu[a][b][c] = 0.0f; cv[a][b][c] = 0.0f; }

    const int ar0 = wm * 32 + (lane & 15);
    const int acs = (lane >> 4);
    const int br0 = wn * 32 + ((lane >> 4) << 3) + (lane & 7);
    const int bcs = ((lane >> 3) & 1);

    for (int kt = 0; kt < UP_NK; kt++) {
        cp_wait<2>(); __syncthreads();
        if (kt + 3 < UP_NK) U_LOAD(kt + 3);
        CP_COMMIT;
        const uint32_t At  = sb + (kt % NSTAGE) * STAGE_BYTES;
        const uint32_t B1t = At + 16384;
        const uint32_t B2t = At + 32768;

        uint32_t afr[2][2][4];         // [buf][mi][4]
        uint32_t bfr[2][8];            // [buf][B1 q0..q3, B2 q0..q3]
#pragma unroll
        for (int mi = 0; mi < 2; mi++)
            ldsm4(afr[0][mi][0], afr[0][mi][1], afr[0][mi][2], afr[0][mi][3],
                  At + sw_off(ar0 + mi * 16, acs));
        {   // step 0 B preload
            int off = sw_off(br0, bcs);
            ldsm4(bfr[0][0], bfr[0][1], bfr[0][2], bfr[0][3], B1t + off);
            ldsm4(bfr[0][4], bfr[0][5], bfr[0][6], bfr[0][7], B2t + off);
        }
#pragma unroll
        for (int s = 0; s < 8; s++) {   // s = ks*2 + bj
            const int ks = s >> 1, bj = s & 1;
            const int cbB = s & 1, nbB = cbB ^ 1;
            const int cbA = ks & 1, nbA = cbA ^ 1;
            if (bj == 0 && ks < 3) {    // preload next ks A frags
#pragma unroll
                for (int mi = 0; mi < 2; mi++)
                    ldsm4(afr[nbA][mi][0], afr[nbA][mi][1], afr[nbA][mi][2], afr[nbA][mi][3],
                          At + sw_off(ar0 + mi * 16, (ks + 1) * 2 + acs));
            }
            if (s < 7) {                // preload next step B frags
                int ns = s + 1;
                int off = sw_off(br0 + ((ns & 1) << 4), ((ns >> 1) << 1) + bcs);
                ldsm4(bfr[nbB][0], bfr[nbB][1], bfr[nbB][2], bfr[nbB][3], B1t + off);
                ldsm4(bfr[nbB][4], bfr[nbB][5], bfr[nbB][6], bfr[nbB][7], B2t + off);
            }
            { uint32_t b[2] = {bfr[cbB][0], bfr[cbB][1]};
              mma16816(cu[0][2 * bj], afr[cbA][0], b);
              mma16816(cu[1][2 * bj], afr[cbA][1], b); }
            { uint32_t b[2] = {bfr[cbB][2], bfr[cbB][3]};
              mma16816(cu[0][2 * bj + 1], afr[cbA][0], b);
              mma16816(cu[1][2 * bj + 1], afr[cbA][1], b); }
            { uint32_t b[2] = {bfr[cbB][4], bfr[cbB][5]};
              mma16816(cv[0][2 * bj], afr[cbA][0], b);
              mma16816(cv[1][2 * bj], afr[cbA][1], b); }
            { uint32_t b[2] = {bfr[cbB][6], bfr[cbB][7]};
              mma16816(cv[0][2 * bj + 1], afr[cbA][0], b);
              mma16816(cv[1][2 * bj + 1], afr[cbA][1], b); }
        }
    }
#undef U_LOAD

    // epilogue: h = silu(u)*v -> fp16 -> g_hH
#pragma unroll
    for (int mi = 0; mi < 2; mi++) {
#pragma unroll
        for (int nj = 0; nj < 4; nj++) {
            int r0 = m0 + wm * 32 + mi * 16 + (lane >> 2);
            int col = bn0 + wn * 32 + nj * 8 + (lane & 3) * 2;
#pragma unroll
            for (int h = 0; h < 2; h++) {
                int r = r0 + 8 * h;
                float f0 = silu_f(cu[mi][nj][2 * h])     * cv[mi][nj][2 * h];
                float f1 = silu_f(cu[mi][nj][2 * h + 1]) * cv[mi][nj][2 * h + 1];
                __half2 hh = __floats2half2_rn(f0, f1);
                *(__half2*)(g_hH + (size_t)r * H_DIM + col) = hh;
            }
        }
    }
}

// ---------------- K5: down GEMM — 512 thr, warp 32x64, A+B preload -------------
__global__ void __launch_bounds__(512, 1) gemm_down_mma() {
    const int e = g_tile_expert[blockIdx.y];
    if (e < 0) return;
    extern __shared__ char raw[];
    char* dsm = (char*)(((uintptr_t)raw + 1023) & ~(uintptr_t)1023);
    const int tid = threadIdx.x;
    const int m0 = blockIdx.y * BM;
    const int bn0 = blockIdx.x * 256;
    const uint32_t sb = smem_u32(dsm);
    const int lane = tid & 31, wid = tid >> 5;
    const int wm = wid & 3, wn = wid >> 2;

    const char* asrc[2]; int dA[2];
    const char* bsrc[4]; int dB[4];
#pragma unroll
    for (int i = 0; i < 2; i++) {
        int idx = tid + i * 512;
        int r = idx >> 3, c = idx & 7;
        dA[i] = sw_off(r, c);
        asrc[i] = (const char*)(g_hH + (size_t)(m0 + r) * H_DIM + c * 8);
    }
#pragma unroll
    for (int i = 0; i < 4; i++) {
        int idx = tid + i * 512;
        int r = idx >> 3, c = idx & 7;
        dB[i] = sw_off(r, c);
        bsrc[i] = (const char*)(g_w3H + ((size_t)e * D_DIM + bn0 + r) * H_DIM + c * 8);
    }

#define D_LOAD(KT) do {                                                         \
    const int _s = (KT) % NSTAGE;                                               \
    const uint32_t _b = sb + _s * STAGE_BYTES;                                  \
    const long _k = (long)(KT) * (BKW * 2);                                     \
    _Pragma("unroll") for (int i = 0; i < 2; i++)                               \
        cp16(_b + dA[i], asrc[i] + _k, 16);                                     \
    _Pragma("unroll") for (int i = 0; i < 4; i++)                               \
        cp16(_b + 16384 + dB[i], bsrc[i] + _k, 16);                             \
    } while (0)

    D_LOAD(0); CP_COMMIT;
    D_LOAD(1); CP_COMMIT;
    D_LOAD(2); CP_COMMIT;

    float acc[2][8][4];
#pragma unroll
    for (int a = 0; a < 2; a++)
#pragma unroll
        for (int b = 0; b < 8; b++)
#pragma unroll
            for (int c = 0; c < 4; c++) acc[a][b][c] = 0.0f;

    const int ar0 = wm * 32 + (lane & 15);
    const int acs = (lane >> 4);
    const int br0 = wn * 64 + ((lane >> 4) << 3) + (lane & 7);
    const int bcs = ((lane >> 3) & 1);

    for (int kt = 0; kt < DN_NK; kt++) {
        cp_wait<2>(); __syncthreads();
        if (kt + 3 < DN_NK) D_LOAD(kt + 3);
        CP_COMMIT;
        const uint32_t At = sb + (kt % NSTAGE) * STAGE_BYTES;
        const uint32_t Bt = At + 16384;

        uint32_t afr[2][2][4];
        uint32_t bfr[2][4];
#pragma unroll
        for (int mi = 0; mi < 2; mi++)
            ldsm4(afr[0][mi][0], afr[0][mi][1], afr[0][mi][2], afr[0][mi][3],
                  At + sw_off(ar0 + mi * 16, acs));
        {
            int off = sw_off(br0, bcs);
            ldsm4(bfr[0][0], bfr[0][1], bfr[0][2], bfr[0][3], Bt + off);
        }
#pragma unroll
        for (int s = 0; s < 16; s++) {  // s = ks*4 + bj
            const int ks = s >> 2, bj = s & 3;
            const int cbB = s & 1, nbB = cbB ^ 1;
            const int cbA = ks & 1, nbA = cbA ^ 1;
            if (bj == 0 && ks < 3) {
#pragma unroll
                for (int mi = 0; mi < 2; mi++)
                    ldsm4(afr[nbA][mi][0], afr[nbA][mi][1], afr[nbA][mi][2], afr[nbA][mi][3],
                          At + sw_off(ar0 + mi * 16, (ks + 1) * 2 + acs));
            }
            if (s < 15) {
                int ns = s + 1;
                int off = sw_off(br0 + ((ns & 3) << 4), ((ns >> 2) << 1) + bcs);
                ldsm4(bfr[nbB][0], bfr[nbB][1], bfr[nbB][2], bfr[nbB][3], Bt + off);
            }
            { uint32_t b[2] = {bfr[cbB][0], bfr[cbB][1]};
              mma16816(acc[0][2 * bj], afr[cbA][0], b);
              mma16816(acc[1][2 * bj], afr[cbA][1], b); }
            { uint32_t b[2] = {bfr[cbB][2], bfr[cbB][3]};
              mma16816(acc[0][2 * bj + 1], afr[cbA][0], b);
              mma16816(acc[1][2 * bj + 1], afr[cbA][1], b); }
        }
    }
#undef D_LOAD

#pragma unroll
    for (int mi = 0; mi < 2; mi++) {
#pragma unroll
        for (int nj = 0; nj < 8; nj++) {
            int r0 = m0 + wm * 32 + mi * 16 + (lane >> 2);
            int col = bn0 + wn * 64 + nj * 8 + (lane & 3) * 2;
            float2 lo = make_float2(acc[mi][nj][0], acc[mi][nj][1]);
            float2 hi = make_float2(acc[mi][nj][2], acc[mi][nj][3]);
            *(float2*)(g_y + (size_t)r0 * D_DIM + col)       = lo;
            *(float2*)(g_y + (size_t)(r0 + 8) * D_DIM + col) = hi;
        }
    }
}

// ---------------- K6: combine ---------------------------------------------------
__global__ void combine_kernel(float* __restrict__ out, int T) {
    const int nq = D_DIM / 4;
    int idx = blockIdx.x * blockDim.x + threadIdx.x;
    if (idx >= T * nq) return;
    int t = idx / nq;
    int dq = idx - t * nq;
    int r0 = g_row_of[2 * t];
    int r1 = g_row_of[2 * t + 1];
    float p0 = g_probs[2 * t];
    float p1 = g_probs[2 * t + 1];
    float4 y0 = *(const float4*)&g_y[(size_t)r0 * D_DIM + dq * 4];
    float4 y1 = *(const float4*)&g_y[(size_t)r1 * D_DIM + dq * 4];
    float4 o;
    o.x = p0 * y0.x + p1 * y1.x;
    o.y = p0 * y0.y + p1 * y1.y;
    o.z = p0 * y0.z + p1 * y1.z;
    o.w = p0 * y0.w + p1 * y1.w;
    *(float4*)&out[(size_t)t * D_DIM + dq * 4] = o;
}

// ---------------- launch ---------------------------------------------------------
extern "C" void kernel_launch(void* const* d_in, const int* in_sizes, int n_in,
                              void* d_out, int out_size) {
    const float* x  = (const float*)d_in[0];
    const float* gw = (const float*)d_in[1];
    const float* w1 = (const float*)d_in[2];
    const float* w2 = (const float*)d_in[3];
    const float* w3 = (const float*)d_in[4];
    float* out = (float*)d_out;

    int T = in_sizes[0] / D_DIM;
    if (T > T_MAX) T = T_MAX;
    int m_tiles = (2 * T) / BM + E_NUM;
    if (m_tiles > MAX_TILES) m_tiles = MAX_TILES;

    cudaFuncSetAttribute(gemm_up_mma,   cudaFuncAttributeMaxDynamicSharedMemorySize, GEMM_SMEM);
    cudaFuncSetAttribute(gemm_down_mma, cudaFuncAttributeMaxDynamicSharedMemorySize, GEMM_SMEM);

    long n4 = (long)E_NUM * H_DIM * D_DIM / 4;
    bool fork = (g_s1 != 0 && g_ef != 0 && g_ej != 0);

    // conv on side stream, overlapped ONLY with init/router/build; join before
    // gemm_up (R8 regression was joining after gemm_up had to share the machine).
    if (fork) {
        cudaEventRecord(g_ef, 0);
        cudaStreamWaitEvent(g_s1, g_ef, 0);
        conv_w_all_kernel<<<(int)((3 * n4 + 255) / 256), 256, 0, g_s1>>>(w1, w2, w3, n4);
        cudaEventRecord(g_ej, g_s1);
    }

    init_kernel<<<1, 32>>>();
    router_kernel<<<(T + 7) / 8, 256>>>(x, gw, T);
    build_kernel<<<m_tiles, BM>>>();

    if (fork) cudaStreamWaitEvent(0, g_ej, 0);
    else conv_w_all_kernel<<<(int)((3 * n4 + 255) / 256), 256>>>(w1, w2, w3, n4);

    gemm_up_mma<<<dim3(H_DIM / 128, m_tiles), 512, GEMM_SMEM>>>();
    gemm_down_mma<<<dim3(D_DIM / 256, m_tiles), 512, GEMM_SMEM>>>();
    combine_kernel<<<(T * (D_DIM / 4) + 255) / 256, 256>>>(out, T);
}

// round 13
// speedup vs baseline: 1.0118x; 1.0118x over previous
#include <cuda_runtime.h>
#include <cuda_fp16.h>
#include <cstdint>

#define D_DIM 1024
#define H_DIM 2048
#define E_NUM 8
#define T_MAX 4096
#define BM 128
#define MAX_TILES 72
#define MAX_ROWS  (MAX_TILES * BM)

#define BKW 64
#define UP_NK 16
#define DN_NK 32
#define STAGE_BYTES 49152
#define NSTAGE 4
#define GEMM_SMEM (NSTAGE * STAGE_BYTES + 1024)

// ---------------- device-global scratch ------------------------------------
__device__ int   g_counts[E_NUM];
__device__ int   g_tile_expert[MAX_TILES];
__device__ int   g_list[E_NUM * T_MAX];
__device__ float g_probs[2 * T_MAX];
__device__ int   g_gather[MAX_ROWS];
__device__ int   g_row_of[2 * T_MAX];
__device__ __half g_xH [(size_t)T_MAX * D_DIM];
__device__ __half g_w1H[(size_t)E_NUM * H_DIM * D_DIM];
__device__ __half g_w2H[(size_t)E_NUM * H_DIM * D_DIM];
__device__ __half g_w3H[(size_t)E_NUM * D_DIM * H_DIM];
__device__ __half g_hH [(size_t)MAX_ROWS * H_DIM];
__device__ float g_y[(size_t)MAX_ROWS * D_DIM];

// ---------------- side stream for conv overlap (load-time init) -------------
static cudaStream_t g_s1 = 0;
static cudaEvent_t  g_ef = 0, g_ej = 0;
namespace {
struct SideInit {
    SideInit() {
        if (cudaStreamCreateWithFlags(&g_s1, cudaStreamNonBlocking) != cudaSuccess) g_s1 = 0;
        if (cudaEventCreateWithFlags(&g_ef, cudaEventDisableTiming) != cudaSuccess) g_ef = 0;
        if (cudaEventCreateWithFlags(&g_ej, cudaEventDisableTiming) != cudaSuccess) g_ej = 0;
    }
};
SideInit s_side_init;
}

// ---------------- helpers ----------------------------------------------------
__device__ __forceinline__ uint32_t smem_u32(const void* p) {
    uint32_t a;
    asm("{ .reg .u64 t; cvta.to.shared.u64 t, %1; cvt.u32.u64 %0, t; }"
        : "=r"(a) : "l"(p));
    return a;
}
__device__ __forceinline__ void ldsm4(uint32_t& r0, uint32_t& r1, uint32_t& r2,
                                      uint32_t& r3, uint32_t addr) {
    asm volatile("ldmatrix.sync.aligned.m8n8.x4.shared.b16 {%0,%1,%2,%3}, [%4];"
                 : "=r"(r0), "=r"(r1), "=r"(r2), "=r"(r3) : "r"(addr));
}
__device__ __forceinline__ void mma16816(float* c, const uint32_t* a,
                                         const uint32_t* b) {
    asm volatile(
        "mma.sync.aligned.m16n8k16.row.col.f32.f16.f16.f32 "
        "{%0,%1,%2,%3},{%4,%5,%6,%7},{%8,%9},{%0,%1,%2,%3};"
        : "+f"(c[0]), "+f"(c[1]), "+f"(c[2]), "+f"(c[3])
        : "r"(a[0]), "r"(a[1]), "r"(a[2]), "r"(a[3]), "r"(b[0]), "r"(b[1]));
}
__device__ __forceinline__ void cp16(uint32_t dst, const void* src, int srcsize) {
    asm volatile("cp.async.cg.shared.global [%0], [%1], 16, %2;"
                 :: "r"(dst), "l"(src), "r"(srcsize) : "memory");
}
#define CP_COMMIT asm volatile("cp.async.commit_group;" ::: "memory")
template <int N>
__device__ __forceinline__ void cp_wait() {
    asm volatile("cp.async.wait_group %0;" :: "n"(N) : "memory");
}
__device__ __forceinline__ float silu_f(float v) { return v / (1.0f + __expf(-v)); }
__device__ __forceinline__ int sw_off(int r, int c) {
    return r * 128 + ((c ^ (r & 7)) << 4);
}

// ---------------- K0: init ----------------------------------------------------
__global__ void init_kernel() {
    if (threadIdx.x < E_NUM) g_counts[threadIdx.x] = 0;
}

// ---------------- K1: router (fused x->fp16) -----------------------------------
__global__ void router_kernel(const float* __restrict__ x,
                              const float* __restrict__ gw, int T) {
    int warp = blockIdx.x * (blockDim.x >> 5) + (threadIdx.x >> 5);
    int lane = threadIdx.x & 31;
    if (warp >= T) return;
    const float* xr = x + (size_t)warp * D_DIM;
    __half* xh = g_xH + (size_t)warp * D_DIM;

    float acc[E_NUM];
#pragma unroll
    for (int e = 0; e < E_NUM; e++) acc[e] = 0.0f;
#pragma unroll
    for (int i = 0; i < D_DIM / 128; i++) {
        int d = i * 128 + lane * 4;
        float4 xv = *(const float4*)(xr + d);
        __half2 h0 = __floats2half2_rn(xv.x, xv.y);
        __half2 h1 = __floats2half2_rn(xv.z, xv.w);
        *(uint2*)(xh + d) = make_uint2(*(uint32_t*)&h0, *(uint32_t*)&h1);
#pragma unroll
        for (int e = 0; e < E_NUM; e++) {
            float4 gv = *(const float4*)(gw + e * D_DIM + d);
            acc[e] += xv.x * gv.x + xv.y * gv.y + xv.z * gv.z + xv.w * gv.w;
        }
    }
#pragma unroll
    for (int e = 0; e < E_NUM; e++) {
#pragma unroll
        for (int off = 16; off > 0; off >>= 1)
            acc[e] += __shfl_xor_sync(0xFFFFFFFFu, acc[e], off);
    }
    if (lane == 0) {
        int e0 = 0; float s0 = acc[0];
#pragma unroll
        for (int e = 1; e < E_NUM; e++) if (acc[e] > s0) { s0 = acc[e]; e0 = e; }
        int e1 = -1; float s1 = -3.4e38f;
#pragma unroll
        for (int e = 0; e < E_NUM; e++)
            if (e != e0 && acc[e] > s1) { s1 = acc[e]; e1 = e; }
        float x1 = __expf(s1 - s0);
        float inv = 1.0f / (1.0f + x1);
        int t = warp;
        g_probs[2 * t] = inv;
        g_probs[2 * t + 1] = x1 * inv;
        int j0 = atomicAdd(&g_counts[e0], 1);
        g_list[e0 * T_MAX + j0] = (t << 1);
        int j1 = atomicAdd(&g_counts[e1], 1);
        g_list[e1 * T_MAX + j1] = (t << 1) | 1;
    }
}

// ---------------- K2: build (inline scan) --------------------------------------
__global__ void build_kernel() {
    __shared__ int s_exp, s_off, s_cnt;
    if (threadIdx.x == 0) {
        int off = 0, nt = 0, my_e = -1, my_off = 0, my_cnt = 0;
#pragma unroll
        for (int e = 0; e < E_NUM; e++) {
            int c = g_counts[e];
            int te = (c + BM - 1) / BM;
            if ((int)blockIdx.x >= nt && (int)blockIdx.x < nt + te) {
                my_e = e; my_off = off; my_cnt = c;
            }
            nt += te;
            off += te * BM;
        }
        g_tile_expert[blockIdx.x] = my_e;
        s_exp = my_e; s_off = my_off; s_cnt = my_cnt;
    }
    __syncthreads();
    int e = s_exp;
    int r = blockIdx.x * BM + threadIdx.x;
    if (e < 0) { g_gather[r] = -1; return; }
    int j = r - s_off;
    if (j < s_cnt) {
        int entry = g_list[e * T_MAX + j];
        g_gather[r] = entry >> 1;
        g_row_of[entry] = r;
    } else {
        g_gather[r] = -1;
    }
}

// ---------------- weight conversion -------------------------------------------
__global__ void conv_w_all_kernel(const float* __restrict__ w1,
                                  const float* __restrict__ w2,
                                  const float* __restrict__ w3, long n4) {
    long i = blockIdx.x * (long)blockDim.x + threadIdx.x;
    if (i >= 3 * n4) return;
    const float* src;
    __half* dst;
    long j;
    if (i < n4)           { src = w1; dst = g_w1H; j = i; }
    else if (i < 2 * n4)  { src = w2; dst = g_w2H; j = i - n4; }
    else                  { src = w3; dst = g_w3H; j = i - 2 * n4; }
    long eb = j * 4;
    float4 v = *(const float4*)(src + eb);
    __half2 h0 = __floats2half2_rn(v.x, v.y);
    __half2 h1 = __floats2half2_rn(v.z, v.w);
    *(uint2*)(dst + eb) = make_uint2(*(uint32_t*)&h0, *(uint32_t*)&h1);
}

// ---------------- K4: up GEMM — R11 core (512 thr, A-preload only) -------------
__global__ void __launch_bounds__(512, 1) gemm_up_mma() {
    const int e = g_tile_expert[blockIdx.y];
    if (e < 0) return;
    extern __shared__ char raw[];
    char* dsm = (char*)(((uintptr_t)raw + 1023) & ~(uintptr_t)1023);
    __shared__ int sg[BM];
    const int tid = threadIdx.x;
    const int m0 = blockIdx.y * BM;
    const int bn0 = blockIdx.x * 128;
    if (tid < BM) sg[tid] = g_gather[m0 + tid];
    __syncthreads();
    const uint32_t sb = smem_u32(dsm);
    const int lane = tid & 31, wid = tid >> 5;
    const int wm = wid & 3, wn = wid >> 2;

    const char* asrc[2]; int asz[2]; int dA[2];
    const char* b1s[2];
    const size_t w2delta = (const char*)g_w2H - (const char*)g_w1H;
#pragma unroll
    for (int i = 0; i < 2; i++) {
        int idx = tid + i * 512;
        int r = idx >> 3, c = idx & 7;
        dA[i] = sw_off(r, c);
        int tok = sg[r];
        asrc[i] = (tok >= 0) ? (const char*)(g_xH + (size_t)tok * D_DIM + c * 8)
                             : (const char*)g_xH;
        asz[i] = (tok >= 0) ? 16 : 0;
        b1s[i] = (const char*)(g_w1H + ((size_t)e * H_DIM + bn0 + r) * D_DIM + c * 8);
    }

#define U_LOAD(KT) do {                                                         \
    const int _s = (KT) % NSTAGE;                                               \
    const uint32_t _b = sb + _s * STAGE_BYTES;                                  \
    const int _k = (KT) * (BKW * 2);                                            \
    _Pragma("unroll") for (int i = 0; i < 2; i++) {                             \
        cp16(_b + dA[i], asrc[i] + _k, asz[i]);                                 \
        cp16(_b + 16384 + dA[i], b1s[i] + _k, 16);                              \
        cp16(_b + 32768 + dA[i], b1s[i] + w2delta + _k, 16);                    \
    } } while (0)

    U_LOAD(0); CP_COMMIT;
    U_LOAD(1); CP_COMMIT;
    U_LOAD(2); CP_COMMIT;

    float cu[2][4][4], cv[2][4][4];
#pragma unroll
    for (int a = 0; a < 2; a++)
#pragma unroll
        for (int b = 0; b < 4; b++)
#pragma unroll
            for (int c = 0; c < 4; c++) { cu[a][b][c] = 0.0f; cv[a][b][c] = 0.0f; }

    const int ar0 = wm * 32 + (lane & 15);
    const int acs = (lane >> 4);

    for (int kt = 0; kt < UP_NK; kt++) {
        cp_wait<2>(); __syncthreads();
        if (kt + 3 < UP_NK) U_LOAD(kt + 3);
        CP_COMMIT;
        const uint32_t At  = sb + (kt % NSTAGE) * STAGE_BYTES;
        const uint32_t B1t = At + 16384;
        const uint32_t B2t = At + 32768;

        uint32_t afr[2][2][4];
#pragma unroll
        for (int mi = 0; mi < 2; mi++)
            ldsm4(afr[0][mi][0], afr[0][mi][1], afr[0][mi][2], afr[0][mi][3],
                  At + sw_off(ar0 + mi * 16, acs));
#pragma unroll
        for (int ks = 0; ks < 4; ks++) {
            const int cb = ks & 1, nb = cb ^ 1;
            if (ks < 3) {
#pragma unroll
                for (int mi = 0; mi < 2; mi++)
                    ldsm4(afr[nb][mi][0], afr[nb][mi][1], afr[nb][mi][2], afr[nb][mi][3],
                          At + sw_off(ar0 + mi * 16, (ks + 1) * 2 + acs));
            }
#pragma unroll
            for (int bj = 0; bj < 2; bj++) {
                int r = wn * 32 + bj * 16 + ((lane >> 4) << 3) + (lane & 7);
                int c = ks * 2 + ((lane >> 3) & 1);
                int off = sw_off(r, c);
                uint32_t q0, q1, q2, q3;
                ldsm4(q0, q1, q2, q3, B1t + off);
                { uint32_t b[2] = {q0, q1};
                  mma16816(cu[0][2 * bj], afr[cb][0], b);
                  mma16816(cu[1][2 * bj], afr[cb][1], b); }
                { uint32_t b[2] = {q2, q3};
                  mma16816(cu[0][2 * bj + 1], afr[cb][0], b);
                  mma16816(cu[1][2 * bj + 1], afr[cb][1], b); }
                ldsm4(q0, q1, q2, q3, B2t + off);
                { uint32_t b[2] = {q0, q1};
                  mma16816(cv[0][2 * bj], afr[cb][0], b);
                  mma16816(cv[1][2 * bj], afr[cb][1], b); }
                { uint32_t b[2] = {q2, q3};
                  mma16816(cv[0][2 * bj + 1], afr[cb][0], b);
                  mma16816(cv[1][2 * bj + 1], afr[cb][1], b); }
            }
        }
    }
#undef U_LOAD

    // epilogue: h = silu(u)*v -> fp16 -> g_hH
#pragma unroll
    for (int mi = 0; mi < 2; mi++) {
#pragma unroll
        for (int nj = 0; nj < 4; nj++) {
            int r0 = m0 + wm * 32 + mi * 16 + (lane >> 2);
            int col = bn0 + wn * 32 + nj * 8 + (lane & 3) * 2;
#pragma unroll
            for (int h = 0; h < 2; h++) {
                int r = r0 + 8 * h;
                float f0 = silu_f(cu[mi][nj][2 * h])     * cv[mi][nj][2 * h];
                float f1 = silu_f(cu[mi][nj][2 * h + 1]) * cv[mi][nj][2 * h + 1];
                __half2 hh = __floats2half2_rn(f0, f1);
                *(__half2*)(g_hH + (size_t)r * H_DIM + col) = hh;
            }
        }
    }
}

// ---------------- K5: down GEMM — R11 core (512 thr, A-preload only) -----------
__global__ void __launch_bounds__(512, 1) gemm_down_mma() {
    const int e = g_tile_expert[blockIdx.y];
    if (e < 0) return;
    extern __shared__ char raw[];
    char* dsm = (char*)(((uintptr_t)raw + 1023) & ~(uintptr_t)1023);
    const int tid = threadIdx.x;
    const int m0 = blockIdx.y * BM;
    const int bn0 = blockIdx.x * 256;
    const uint32_t sb = smem_u32(dsm);
    const int lane = tid & 31, wid = tid >> 5;
    const int wm = wid & 3, wn = wid >> 2;

    const char* asrc[2]; int dA[2];
    const char* bsrc[4]; int dB[4];
#pragma unroll
    for (int i = 0; i < 2; i++) {
        int idx = tid + i * 512;
        int r = idx >> 3, c = idx & 7;
        dA[i] = sw_off(r, c);
        asrc[i] = (const char*)(g_hH + (size_t)(m0 + r) * H_DIM + c * 8);
    }
#pragma unroll
    for (int i = 0; i < 4; i++) {
        int idx = tid + i * 512;
        int r = idx >> 3, c = idx & 7;
        dB[i] = sw_off(r, c);
        bsrc[i] = (const char*)(g_w3H + ((size_t)e * D_DIM + bn0 + r) * H_DIM + c * 8);
    }

#define D_LOAD(KT) do {                                                         \
    const int _s = (KT) % NSTAGE;                                               \
    const uint32_t _b = sb + _s * STAGE_BYTES;                                  \
    const long _k = (long)(KT) * (BKW * 2);                                     \
    _Pragma("unroll") for (int i = 0; i < 2; i++)                               \
        cp16(_b + dA[i], asrc[i] + _k, 16);                                     \
    _Pragma("unroll") for (int i = 0; i < 4; i++)                               \
        cp16(_b + 16384 + dB[i], bsrc[i] + _k, 16);                             \
    } while (0)

    D_LOAD(0); CP_COMMIT;
    D_LOAD(1); CP_COMMIT;
    D_LOAD(2); CP_COMMIT;

    float acc[2][8][4];
#pragma unroll
    for (int a = 0; a < 2; a++)
#pragma unroll
        for (int b = 0; b < 8; b++)
#pragma unroll
            for (int c = 0; c < 4; c++) acc[a][b][c] = 0.0f;

    const int ar0 = wm * 32 + (lane & 15);
    const int acs = (lane >> 4);

    for (int kt = 0; kt < DN_NK; kt++) {
        cp_wait<2>(); __syncthreads();
        if (kt + 3 < DN_NK) D_LOAD(kt + 3);
        CP_COMMIT;
        const uint32_t At = sb + (kt % NSTAGE) * STAGE_BYTES;
        const uint32_t Bt = At + 16384;

        uint32_t afr[2][2][4];
#pragma unroll
        for (int mi = 0; mi < 2; mi++)
            ldsm4(afr[0][mi][0], afr[0][mi][1], afr[0][mi][2], afr[0][mi][3],
                  At + sw_off(ar0 + mi * 16, acs));
#pragma unroll
        for (int ks = 0; ks < 4; ks++) {
            const int cb = ks & 1, nb = cb ^ 1;
            if (ks < 3) {
#pragma unroll
                for (int mi = 0; mi < 2; mi++)
                    ldsm4(afr[nb][mi][0], afr[nb][mi][1], afr[nb][mi][2], afr[nb][mi][3],
                          At + sw_off(ar0 + mi * 16, (ks + 1) * 2 + acs));
            }
#pragma unroll
            for (int bj = 0; bj < 4; bj++) {
                int r = wn * 64 + bj * 16 + ((lane >> 4) << 3) + (lane & 7);
                int c = ks * 2 + ((lane >> 3) & 1);
                uint32_t q0, q1, q2, q3;
                ldsm4(q0, q1, q2, q3, Bt + sw_off(r, c));
                { uint32_t b[2] = {q0, q1};
                  mma16816(acc[0][2 * bj], afr[cb][0], b);
                  mma16816(acc[1][2 * bj], afr[cb][1], b); }
                { uint32_t b[2] = {q2, q3};
                  mma16816(acc[0][2 * bj + 1], afr[cb][0], b);
                  mma16816(acc[1][2 * bj + 1], afr[cb][1], b); }
            }
        }
    }
#undef D_LOAD

#pragma unroll
    for (int mi = 0; mi < 2; mi++) {
#pragma unroll
        for (int nj = 0; nj < 8; nj++) {
            int r0 = m0 + wm * 32 + mi * 16 + (lane >> 2);
            int col = bn0 + wn * 64 + nj * 8 + (lane & 3) * 2;
            float2 lo = make_float2(acc[mi][nj][0], acc[mi][nj][1]);
            float2 hi = make_float2(acc[mi][nj][2], acc[mi][nj][3]);
            *(float2*)(g_y + (size_t)r0 * D_DIM + col)       = lo;
            *(float2*)(g_y + (size_t)(r0 + 8) * D_DIM + col) = hi;
        }
    }
}

// ---------------- K6: combine ---------------------------------------------------
__global__ void combine_kernel(float* __restrict__ out, int T) {
    const int nq = D_DIM / 4;
    int idx = blockIdx.x * blockDim.x + threadIdx.x;
    if (idx >= T * nq) return;
    int t = idx / nq;
    int dq = idx - t * nq;
    int r0 = g_row_of[2 * t];
    int r1 = g_row_of[2 * t + 1];
    float p0 = g_probs[2 * t];
    float p1 = g_probs[2 * t + 1];
    float4 y0 = *(const float4*)&g_y[(size_t)r0 * D_DIM + dq * 4];
    float4 y1 = *(const float4*)&g_y[(size_t)r1 * D_DIM + dq * 4];
    float4 o;
    o.x = p0 * y0.x + p1 * y1.x;
    o.y = p0 * y0.y + p1 * y1.y;
    o.z = p0 * y0.z + p1 * y1.z;
    o.w = p0 * y0.w + p1 * y1.w;
    *(float4*)&out[(size_t)t * D_DIM + dq * 4] = o;
}

// ---------------- launch ---------------------------------------------------------
extern "C" void kernel_launch(void* const* d_in, const int* in_sizes, int n_in,
                              void* d_out, int out_size) {
    const float* x  = (const float*)d_in[0];
    const float* gw = (const float*)d_in[1];
    const float* w1 = (const float*)d_in[2];
    const float* w2 = (const float*)d_in[3];
    const float* w3 = (const float*)d_in[4];
    float* out = (float*)d_out;

    int T = in_sizes[0] / D_DIM;
    if (T > T_MAX) T = T_MAX;
    int m_tiles = (2 * T) / BM + E_NUM;
    if (m_tiles > MAX_TILES) m_tiles = MAX_TILES;

    cudaFuncSetAttribute(gemm_up_mma,   cudaFuncAttributeMaxDynamicSharedMemorySize, GEMM_SMEM);
    cudaFuncSetAttribute(gemm_down_mma, cudaFuncAttributeMaxDynamicSharedMemorySize, GEMM_SMEM);

    long n4 = (long)E_NUM * H_DIM * D_DIM / 4;
    bool fork = (g_s1 != 0 && g_ef != 0 && g_ej != 0);

    // conv on side stream, overlapped ONLY with init/router/build
    if (fork) {
        cudaEventRecord(g_ef, 0);
        cudaStreamWaitEvent(g_s1, g_ef, 0);
        conv_w_all_kernel<<<(int)((3 * n4 + 255) / 256), 256, 0, g_s1>>>(w1, w2, w3, n4);
        cudaEventRecord(g_ej, g_s1);
    }

    init_kernel<<<1, 32>>>();
    router_kernel<<<(T + 7) / 8, 256>>>(x, gw, T);
    build_kernel<<<m_tiles, BM>>>();

    if (fork) cudaStreamWaitEvent(0, g_ej, 0);
    else conv_w_all_kernel<<<(int)((3 * n4 + 255) / 256), 256>>>(w1, w2, w3, n4);

    gemm_up_mma<<<dim3(H_DIM / 128, m_tiles), 512, GEMM_SMEM>>>();
    gemm_down_mma<<<dim3(D_DIM / 256, m_tiles), 512, GEMM_SMEM>>>();
    combine_kernel<<<(T * (D_DIM / 4) + 255) / 256, 256>>>(out, T);
}

// round 14
// speedup vs baseline: 1.0173x; 1.0054x over previous
#include <cuda_runtime.h>
#include <cuda_fp16.h>
#include <cstdint>

#define D_DIM 1024
#define H_DIM 2048
#define E_NUM 8
#define T_MAX 4096
#define BM 128
#define MAX_TILES 72
#define MAX_ROWS  (MAX_TILES * BM)

#define BKW 64
#define UP_NK 16
#define DN_NK 32
#define STAGE_BYTES 49152
#define NSTAGE 4
#define GEMM_SMEM (NSTAGE * STAGE_BYTES + 1024)

// ---------------- device-global scratch ------------------------------------
__device__ int   g_counts[E_NUM];
__device__ int   g_tile_expert[MAX_TILES];
__device__ int   g_list[E_NUM * T_MAX];
__device__ float g_probs[2 * T_MAX];
__device__ int   g_gather[MAX_ROWS];
__device__ float g_rowprob[MAX_ROWS];
__device__ __half g_xH [(size_t)T_MAX * D_DIM];
__device__ __half g_w1H[(size_t)E_NUM * H_DIM * D_DIM];
__device__ __half g_w2H[(size_t)E_NUM * H_DIM * D_DIM];
__device__ __half g_w3H[(size_t)E_NUM * D_DIM * H_DIM];
__device__ __half g_hH [(size_t)MAX_ROWS * H_DIM];

// ---------------- side stream for conv overlap (load-time init) -------------
static cudaStream_t g_s1 = 0;
static cudaEvent_t  g_ef = 0, g_ej = 0;
namespace {
struct SideInit {
    SideInit() {
        if (cudaStreamCreateWithFlags(&g_s1, cudaStreamNonBlocking) != cudaSuccess) g_s1 = 0;
        if (cudaEventCreateWithFlags(&g_ef, cudaEventDisableTiming) != cudaSuccess) g_ef = 0;
        if (cudaEventCreateWithFlags(&g_ej, cudaEventDisableTiming) != cudaSuccess) g_ej = 0;
    }
};
SideInit s_side_init;
}

// ---------------- helpers ----------------------------------------------------
__device__ __forceinline__ uint32_t smem_u32(const void* p) {
    uint32_t a;
    asm("{ .reg .u64 t; cvta.to.shared.u64 t, %1; cvt.u32.u64 %0, t; }"
        : "=r"(a) : "l"(p));
    return a;
}
__device__ __forceinline__ void ldsm4(uint32_t& r0, uint32_t& r1, uint32_t& r2,
                                      uint32_t& r3, uint32_t addr) {
    asm volatile("ldmatrix.sync.aligned.m8n8.x4.shared.b16 {%0,%1,%2,%3}, [%4];"
                 : "=r"(r0), "=r"(r1), "=r"(r2), "=r"(r3) : "r"(addr));
}
__device__ __forceinline__ void mma16816(float* c, const uint32_t* a,
                                         const uint32_t* b) {
    asm volatile(
        "mma.sync.aligned.m16n8k16.row.col.f32.f16.f16.f32 "
        "{%0,%1,%2,%3},{%4,%5,%6,%7},{%8,%9},{%0,%1,%2,%3};"
        : "+f"(c[0]), "+f"(c[1]), "+f"(c[2]), "+f"(c[3])
        : "r"(a[0]), "r"(a[1]), "r"(a[2]), "r"(a[3]), "r"(b[0]), "r"(b[1]));
}
__device__ __forceinline__ void cp16(uint32_t dst, const void* src, int srcsize) {
    asm volatile("cp.async.cg.shared.global [%0], [%1], 16, %2;"
                 :: "r"(dst), "l"(src), "r"(srcsize) : "memory");
}
#define CP_COMMIT asm volatile("cp.async.commit_group;" ::: "memory")
template <int N>
__device__ __forceinline__ void cp_wait() {
    asm volatile("cp.async.wait_group %0;" :: "n"(N) : "memory");
}
__device__ __forceinline__ void red2(float* addr, float a, float b) {
    asm volatile("red.global.add.v2.f32 [%0], {%1, %2};"
                 :: "l"(addr), "f"(a), "f"(b) : "memory");
}
__device__ __forceinline__ float silu_f(float v) { return v / (1.0f + __expf(-v)); }
__device__ __forceinline__ int sw_off(int r, int c) {
    return r * 128 + ((c ^ (r & 7)) << 4);
}

// ---------------- K0: zero out + expert counters --------------------------------
__global__ void zero_out_kernel(float* __restrict__ out, int total4) {
    int i = blockIdx.x * blockDim.x + threadIdx.x;
    if (i < total4) *(float4*)(out + i * 4) = make_float4(0, 0, 0, 0);
    if (blockIdx.x == 0 && threadIdx.x < E_NUM) g_counts[threadIdx.x] = 0;
}

// ---------------- K1: router (fused x->fp16) -----------------------------------
__global__ void router_kernel(const float* __restrict__ x,
                              const float* __restrict__ gw, int T) {
    int warp = blockIdx.x * (blockDim.x >> 5) + (threadIdx.x >> 5);
    int lane = threadIdx.x & 31;
    if (warp >= T) return;
    const float* xr = x + (size_t)warp * D_DIM;
    __half* xh = g_xH + (size_t)warp * D_DIM;

    float acc[E_NUM];
#pragma unroll
    for (int e = 0; e < E_NUM; e++) acc[e] = 0.0f;
#pragma unroll
    for (int i = 0; i < D_DIM / 128; i++) {
        int d = i * 128 + lane * 4;
        float4 xv = *(const float4*)(xr + d);
        __half2 h0 = __floats2half2_rn(xv.x, xv.y);
        __half2 h1 = __floats2half2_rn(xv.z, xv.w);
        *(uint2*)(xh + d) = make_uint2(*(uint32_t*)&h0, *(uint32_t*)&h1);
#pragma unroll
        for (int e = 0; e < E_NUM; e++) {
            float4 gv = *(const float4*)(gw + e * D_DIM + d);
            acc[e] += xv.x * gv.x + xv.y * gv.y + xv.z * gv.z + xv.w * gv.w;
        }
    }
#pragma unroll
    for (int e = 0; e < E_NUM; e++) {
#pragma unroll
        for (int off = 16; off > 0; off >>= 1)
            acc[e] += __shfl_xor_sync(0xFFFFFFFFu, acc[e], off);
    }
    if (lane == 0) {
        int e0 = 0; float s0 = acc[0];
#pragma unroll
        for (int e = 1; e < E_NUM; e++) if (acc[e] > s0) { s0 = acc[e]; e0 = e; }
        int e1 = -1; float s1 = -3.4e38f;
#pragma unroll
        for (int e = 0; e < E_NUM; e++)
            if (e != e0 && acc[e] > s1) { s1 = acc[e]; e1 = e; }
        float x1 = __expf(s1 - s0);
        float inv = 1.0f / (1.0f + x1);
        int t = warp;
        g_probs[2 * t] = inv;
        g_probs[2 * t + 1] = x1 * inv;
        int j0 = atomicAdd(&g_counts[e0], 1);
        g_list[e0 * T_MAX + j0] = (t << 1);
        int j1 = atomicAdd(&g_counts[e1], 1);
        g_list[e1 * T_MAX + j1] = (t << 1) | 1;
    }
}

// ---------------- K2: build (inline scan, + per-row prob) ----------------------
__global__ void build_kernel() {
    __shared__ int s_exp, s_off, s_cnt;
    if (threadIdx.x == 0) {
        int off = 0, nt = 0, my_e = -1, my_off = 0, my_cnt = 0;
#pragma unroll
        for (int e = 0; e < E_NUM; e++) {
            int c = g_counts[e];
            int te = (c + BM - 1) / BM;
            if ((int)blockIdx.x >= nt && (int)blockIdx.x < nt + te) {
                my_e = e; my_off = off; my_cnt = c;
            }
            nt += te;
            off += te * BM;
        }
        g_tile_expert[blockIdx.x] = my_e;
        s_exp = my_e; s_off = my_off; s_cnt = my_cnt;
    }
    __syncthreads();
    int e = s_exp;
    int r = blockIdx.x * BM + threadIdx.x;
    if (e < 0) { g_gather[r] = -1; g_rowprob[r] = 0.0f; return; }
    int j = r - s_off;
    if (j < s_cnt) {
        int entry = g_list[e * T_MAX + j];
        g_gather[r] = entry >> 1;
        g_rowprob[r] = g_probs[entry];
    } else {
        g_gather[r] = -1;
        g_rowprob[r] = 0.0f;
    }
}

// ---------------- weight conversion -------------------------------------------
__global__ void conv_w_all_kernel(const float* __restrict__ w1,
                                  const float* __restrict__ w2,
                                  const float* __restrict__ w3, long n4) {
    long i = blockIdx.x * (long)blockDim.x + threadIdx.x;
    if (i >= 3 * n4) return;
    const float* src;
    __half* dst;
    long j;
    if (i < n4)           { src = w1; dst = g_w1H; j = i; }
    else if (i < 2 * n4)  { src = w2; dst = g_w2H; j = i - n4; }
    else                  { src = w3; dst = g_w3H; j = i - 2 * n4; }
    long eb = j * 4;
    float4 v = *(const float4*)(src + eb);
    __half2 h0 = __floats2half2_rn(v.x, v.y);
    __half2 h1 = __floats2half2_rn(v.z, v.w);
    *(uint2*)(dst + eb) = make_uint2(*(uint32_t*)&h0, *(uint32_t*)&h1);
}

// ---------------- K4: up GEMM — R11 core (512 thr, A-preload) -------------------
__global__ void __launch_bounds__(512, 1) gemm_up_mma() {
    const int e = g_tile_expert[blockIdx.y];
    if (e < 0) return;
    extern __shared__ char raw[];
    char* dsm = (char*)(((uintptr_t)raw + 1023) & ~(uintptr_t)1023);
    __shared__ int sg[BM];
    const int tid = threadIdx.x;
    const int m0 = blockIdx.y * BM;
    const int bn0 = blockIdx.x * 128;
    if (tid < BM) sg[tid] = g_gather[m0 + tid];
    __syncthreads();
    const uint32_t sb = smem_u32(dsm);
    const int lane = tid & 31, wid = tid >> 5;
    const int wm = wid & 3, wn = wid >> 2;

    const char* asrc[2]; int asz[2]; int dA[2];
    const char* b1s[2];
    const size_t w2delta = (const char*)g_w2H - (const char*)g_w1H;
#pragma unroll
    for (int i = 0; i < 2; i++) {
        int idx = tid + i * 512;
        int r = idx >> 3, c = idx & 7;
        dA[i] = sw_off(r, c);
        int tok = sg[r];
        asrc[i] = (tok >= 0) ? (const char*)(g_xH + (size_t)tok * D_DIM + c * 8)
                             : (const char*)g_xH;
        asz[i] = (tok >= 0) ? 16 : 0;
        b1s[i] = (const char*)(g_w1H + ((size_t)e * H_DIM + bn0 + r) * D_DIM + c * 8);
    }

#define U_LOAD(KT) do {                                                         \
    const int _s = (KT) % NSTAGE;                                               \
    const uint32_t _b = sb + _s * STAGE_BYTES;                                  \
    const int _k = (KT) * (BKW * 2);                                            \
    _Pragma("unroll") for (int i = 0; i < 2; i++) {                             \
        cp16(_b + dA[i], asrc[i] + _k, asz[i]);                                 \
        cp16(_b + 16384 + dA[i], b1s[i] + _k, 16);                              \
        cp16(_b + 32768 + dA[i], b1s[i] + w2delta + _k, 16);                    \
    } } while (0)

    U_LOAD(0); CP_COMMIT;
    U_LOAD(1); CP_COMMIT;
    U_LOAD(2); CP_COMMIT;

    float cu[2][4][4], cv[2][4][4];
#pragma unroll
    for (int a = 0; a < 2; a++)
#pragma unroll
        for (int b = 0; b < 4; b++)
#pragma unroll
            for (int c = 0; c < 4; c++) { cu[a][b][c] = 0.0f; cv[a][b][c] = 0.0f; }

    const int ar0 = wm * 32 + (lane & 15);
    const int acs = (lane >> 4);

    for (int kt = 0; kt < UP_NK; kt++) {
        cp_wait<2>(); __syncthreads();
        if (kt + 3 < UP_NK) U_LOAD(kt + 3);
        CP_COMMIT;
        const uint32_t At  = sb + (kt % NSTAGE) * STAGE_BYTES;
        const uint32_t B1t = At + 16384;
        const uint32_t B2t = At + 32768;

        uint32_t afr[2][2][4];
#pragma unroll
        for (int mi = 0; mi < 2; mi++)
            ldsm4(afr[0][mi][0], afr[0][mi][1], afr[0][mi][2], afr[0][mi][3],
                  At + sw_off(ar0 + mi * 16, acs));
#pragma unroll
        for (int ks = 0; ks < 4; ks++) {
            const int cb = ks & 1, nb = cb ^ 1;
            if (ks < 3) {
#pragma unroll
                for (int mi = 0; mi < 2; mi++)
                    ldsm4(afr[nb][mi][0], afr[nb][mi][1], afr[nb][mi][2], afr[nb][mi][3],
                          At + sw_off(ar0 + mi * 16, (ks + 1) * 2 + acs));
            }
#pragma unroll
            for (int bj = 0; bj < 2; bj++) {
                int r = wn * 32 + bj * 16 + ((lane >> 4) << 3) + (lane & 7);
                int c = ks * 2 + ((lane >> 3) & 1);
                int off = sw_off(r, c);
                uint32_t q0, q1, q2, q3;
                ldsm4(q0, q1, q2, q3, B1t + off);
                { uint32_t b[2] = {q0, q1};
                  mma16816(cu[0][2 * bj], afr[cb][0], b);
                  mma16816(cu[1][2 * bj], afr[cb][1], b); }
                { uint32_t b[2] = {q2, q3};
                  mma16816(cu[0][2 * bj + 1], afr[cb][0], b);
                  mma16816(cu[1][2 * bj + 1], afr[cb][1], b); }
                ldsm4(q0, q1, q2, q3, B2t + off);
                { uint32_t b[2] = {q0, q1};
                  mma16816(cv[0][2 * bj], afr[cb][0], b);
                  mma16816(cv[1][2 * bj], afr[cb][1], b); }
                { uint32_t b[2] = {q2, q3};
                  mma16816(cv[0][2 * bj + 1], afr[cb][0], b);
                  mma16816(cv[1][2 * bj + 1], afr[cb][1], b); }
            }
        }
    }
#undef U_LOAD

#pragma unroll
    for (int mi = 0; mi < 2; mi++) {
#pragma unroll
        for (int nj = 0; nj < 4; nj++) {
            int r0 = m0 + wm * 32 + mi * 16 + (lane >> 2);
            int col = bn0 + wn * 32 + nj * 8 + (lane & 3) * 2;
#pragma unroll
            for (int h = 0; h < 2; h++) {
                int r = r0 + 8 * h;
                float f0 = silu_f(cu[mi][nj][2 * h])     * cv[mi][nj][2 * h];
                float f1 = silu_f(cu[mi][nj][2 * h + 1]) * cv[mi][nj][2 * h + 1];
                __half2 hh = __floats2half2_rn(f0, f1);
                *(__half2*)(g_hH + (size_t)r * H_DIM + col) = hh;
            }
        }
    }
}

// ---------------- K5: down GEMM — fused combine epilogue (red.global.v2) -------
__global__ void __launch_bounds__(512, 1) gemm_down_mma(float* __restrict__ out) {
    const int e = g_tile_expert[blockIdx.y];
    if (e < 0) return;
    extern __shared__ char raw[];
    char* dsm = (char*)(((uintptr_t)raw + 1023) & ~(uintptr_t)1023);
    const int tid = threadIdx.x;
    const int m0 = blockIdx.y * BM;
    const int bn0 = blockIdx.x * 256;
    const uint32_t sb = smem_u32(dsm);
    const int lane = tid & 31, wid = tid >> 5;
    const int wm = wid & 3, wn = wid >> 2;

    const char* asrc[2]; int dA[2];
    const char* bsrc[4]; int dB[4];
#pragma unroll
    for (int i = 0; i < 2; i++) {
        int idx = tid + i * 512;
        int r = idx >> 3, c = idx & 7;
        dA[i] = sw_off(r, c);
        asrc[i] = (const char*)(g_hH + (size_t)(m0 + r) * H_DIM + c * 8);
    }
#pragma unroll
    for (int i = 0; i < 4; i++) {
        int idx = tid + i * 512;
        int r = idx >> 3, c = idx & 7;
        dB[i] = sw_off(r, c);
        bsrc[i] = (const char*)(g_w3H + ((size_t)e * D_DIM + bn0 + r) * H_DIM + c * 8);
    }

#define D_LOAD(KT) do {                                                         \
    const int _s = (KT) % NSTAGE;                                               \
    const uint32_t _b = sb + _s * STAGE_BYTES;                                  \
    const long _k = (long)(KT) * (BKW * 2);                                     \
    _Pragma("unroll") for (int i = 0; i < 2; i++)                               \
        cp16(_b + dA[i], asrc[i] + _k, 16);                                     \
    _Pragma("unroll") for (int i = 0; i < 4; i++)                               \
        cp16(_b + 16384 + dB[i], bsrc[i] + _k, 16);                             \
    } while (0)

    D_LOAD(0); CP_COMMIT;
    D_LOAD(1); CP_COMMIT;
    D_LOAD(2); CP_COMMIT;

    float acc[2][8][4];
#pragma unroll
    for (int a = 0; a < 2; a++)
#pragma unroll
        for (int b = 0; b < 8; b++)
#pragma unroll
            for (int c = 0; c < 4; c++) acc[a][b][c] = 0.0f;

    const int ar0 = wm * 32 + (lane & 15);
    const int acs = (lane >> 4);

    for (int kt = 0; kt < DN_NK; kt++) {
        cp_wait<2>(); __syncthreads();
        if (kt + 3 < DN_NK) D_LOAD(kt + 3);
        CP_COMMIT;
        const uint32_t At = sb + (kt % NSTAGE) * STAGE_BYTES;
        const uint32_t Bt = At + 16384;

        uint32_t afr[2][2][4];
#pragma unroll
        for (int mi = 0; mi < 2; mi++)
            ldsm4(afr[0][mi][0], afr[0][mi][1], afr[0][mi][2], afr[0][mi][3],
                  At + sw_off(ar0 + mi * 16, acs));
#pragma unroll
        for (int ks = 0; ks < 4; ks++) {
            const int cb = ks & 1, nb = cb ^ 1;
            if (ks < 3) {
#pragma unroll
                for (int mi = 0; mi < 2; mi++)
                    ldsm4(afr[nb][mi][0], afr[nb][mi][1], afr[nb][mi][2], afr[nb][mi][3],
                          At + sw_off(ar0 + mi * 16, (ks + 1) * 2 + acs));
            }
#pragma unroll
            for (int bj = 0; bj < 4; bj++) {
                int r = wn * 64 + bj * 16 + ((lane >> 4) << 3) + (lane & 7);
                int c = ks * 2 + ((lane >> 3) & 1);
                uint32_t q0, q1, q2, q3;
                ldsm4(q0, q1, q2, q3, Bt + sw_off(r, c));
                { uint32_t b[2] = {q0, q1};
                  mma16816(acc[0][2 * bj], afr[cb][0], b);
                  mma16816(acc[1][2 * bj], afr[cb][1], b); }
                { uint32_t b[2] = {q2, q3};
                  mma16816(acc[0][2 * bj + 1], afr[cb][0], b);
                  mma16816(acc[1][2 * bj + 1], afr[cb][1], b); }
            }
        }
    }
#undef D_LOAD

    // fused combine: out[tok] += p * acc  (2 atomic adds per element, IEEE-commutative)
    int   tk[2][2];
    float pp[2][2];
#pragma unroll
    for (int mi = 0; mi < 2; mi++) {
        int r0 = m0 + wm * 32 + mi * 16 + (lane >> 2);
#pragma unroll
        for (int h = 0; h < 2; h++) {
            int r = r0 + 8 * h;
            tk[mi][h] = g_gather[r];
            pp[mi][h] = g_rowprob[r];
        }
    }
#pragma unroll
    for (int mi = 0; mi < 2; mi++) {
#pragma unroll
        for (int nj = 0; nj < 8; nj++) {
            int col = bn0 + wn * 64 + nj * 8 + (lane & 3) * 2;
            if (tk[mi][0] >= 0)
                red2(out + (size_t)tk[mi][0] * D_DIM + col,
                     pp[mi][0] * acc[mi][nj][0], pp[mi][0] * acc[mi][nj][1]);
            if (tk[mi][1] >= 0)
                red2(out + (size_t)tk[mi][1] * D_DIM + col,
                     pp[mi][1] * acc[mi][nj][2], pp[mi][1] * acc[mi][nj][3]);
        }
    }
}

// ---------------- launch ---------------------------------------------------------
extern "C" void kernel_launch(void* const* d_in, const int* in_sizes, int n_in,
                              void* d_out, int out_size) {
    const float* x  = (const float*)d_in[0];
    const float* gw = (const float*)d_in[1];
    const float* w1 = (const float*)d_in[2];
    const float* w2 = (const float*)d_in[3];
    const float* w3 = (const float*)d_in[4];
    float* out = (float*)d_out;

    int T = in_sizes[0] / D_DIM;
    if (T > T_MAX) T = T_MAX;
    int m_tiles = (2 * T) / BM + E_NUM;
    if (m_tiles > MAX_TILES) m_tiles = MAX_TILES;

    cudaFuncSetAttribute(gemm_up_mma,   cudaFuncAttributeMaxDynamicSharedMemorySize, GEMM_SMEM);
    cudaFuncSetAttribute(gemm_down_mma, cudaFuncAttributeMaxDynamicSharedMemorySize, GEMM_SMEM);

    long n4 = (long)E_NUM * H_DIM * D_DIM / 4;
    bool fork = (g_s1 != 0 && g_ef != 0 && g_ej != 0);

    if (fork) {
        cudaEventRecord(g_ef, 0);
        cudaStreamWaitEvent(g_s1, g_ef, 0);
        conv_w_all_kernel<<<(int)((3 * n4 + 255) / 256), 256, 0, g_s1>>>(w1, w2, w3, n4);
        cudaEventRecord(g_ej, g_s1);
    }

    int out4 = T * (D_DIM / 4);
    zero_out_kernel<<<(out4 + 255) / 256, 256>>>(out, out4);
    router_kernel<<<(T + 7) / 8, 256>>>(x, gw, T);
    build_kernel<<<m_tiles, BM>>>();

    if (fork) cudaStreamWaitEvent(0, g_ej, 0);
    else conv_w_all_kernel<<<(int)((3 * n4 + 255) / 256), 256>>>(w1, w2, w3, n4);

    gemm_up_mma<<<dim3(H_DIM / 128, m_tiles), 512, GEMM_SMEM>>>();
    gemm_down_mma<<<dim3(D_DIM / 256, m_tiles), 512, GEMM_SMEM>>>(out);
}

// round 15
// speedup vs baseline: 1.0217x; 1.0044x over previous
#include <cuda_runtime.h>
#include <cuda_fp16.h>
#include <cstdint>

#define D_DIM 1024
#define H_DIM 2048
#define E_NUM 8
#define T_MAX 4096
#define BM 128
#define MAX_TILES 72
#define MAX_ROWS  (MAX_TILES * BM)

#define BKW 64
#define UP_NK 16
#define DN_NK 32
#define STAGE_BYTES 49152
#define NSTAGE 4
#define GEMM_SMEM (NSTAGE * STAGE_BYTES + 1024)

// ---------------- device-global scratch ------------------------------------
__device__ int   g_counts[E_NUM];
__device__ int   g_tile_expert[MAX_TILES];
__device__ int   g_list[E_NUM * T_MAX];
__device__ float g_probs[2 * T_MAX];
__device__ int   g_gather[MAX_ROWS];
__device__ float g_rowprob[MAX_ROWS];
__device__ __half g_xH [(size_t)T_MAX * D_DIM];
__device__ __half g_w1H[(size_t)E_NUM * H_DIM * D_DIM];
__device__ __half g_w2H[(size_t)E_NUM * H_DIM * D_DIM];
__device__ __half g_w3H[(size_t)E_NUM * D_DIM * H_DIM];
__device__ __half g_hH [(size_t)MAX_ROWS * H_DIM];

// ---------------- side stream for conv overlap (load-time init) -------------
static cudaStream_t g_s1 = 0;
static cudaEvent_t  g_ef = 0, g_ej = 0;
namespace {
struct SideInit {
    SideInit() {
        if (cudaStreamCreateWithFlags(&g_s1, cudaStreamNonBlocking) != cudaSuccess) g_s1 = 0;
        if (cudaEventCreateWithFlags(&g_ef, cudaEventDisableTiming) != cudaSuccess) g_ef = 0;
        if (cudaEventCreateWithFlags(&g_ej, cudaEventDisableTiming) != cudaSuccess) g_ej = 0;
    }
};
SideInit s_side_init;
}

// ---------------- helpers ----------------------------------------------------
__device__ __forceinline__ uint32_t smem_u32(const void* p) {
    uint32_t a;
    asm("{ .reg .u64 t; cvta.to.shared.u64 t, %1; cvt.u32.u64 %0, t; }"
        : "=r"(a) : "l"(p));
    return a;
}
__device__ __forceinline__ void ldsm4(uint32_t& r0, uint32_t& r1, uint32_t& r2,
                                      uint32_t& r3, uint32_t addr) {
    asm volatile("ldmatrix.sync.aligned.m8n8.x4.shared.b16 {%0,%1,%2,%3}, [%4];"
                 : "=r"(r0), "=r"(r1), "=r"(r2), "=r"(r3) : "r"(addr));
}
__device__ __forceinline__ void mma16816(float* c, const uint32_t* a,
                                         const uint32_t* b) {
    asm volatile(
        "mma.sync.aligned.m16n8k16.row.col.f32.f16.f16.f32 "
        "{%0,%1,%2,%3},{%4,%5,%6,%7},{%8,%9},{%0,%1,%2,%3};"
        : "+f"(c[0]), "+f"(c[1]), "+f"(c[2]), "+f"(c[3])
        : "r"(a[0]), "r"(a[1]), "r"(a[2]), "r"(a[3]), "r"(b[0]), "r"(b[1]));
}
__device__ __forceinline__ void cp16(uint32_t dst, const void* src, int srcsize) {
    asm volatile("cp.async.cg.shared.global [%0], [%1], 16, %2;"
                 :: "r"(dst), "l"(src), "r"(srcsize) : "memory");
}
#define CP_COMMIT asm volatile("cp.async.commit_group;" ::: "memory")
template <int N>
__device__ __forceinline__ void cp_wait() {
    asm volatile("cp.async.wait_group %0;" :: "n"(N) : "memory");
}
__device__ __forceinline__ void red2(float* addr, float a, float b) {
    asm volatile("red.global.add.v2.f32 [%0], {%1, %2};"
                 :: "l"(addr), "f"(a), "f"(b) : "memory");
}
__device__ __forceinline__ float silu_f(float v) { return v / (1.0f + __expf(-v)); }
__device__ __forceinline__ int sw_off(int r, int c) {
    return r * 128 + ((c ^ (r & 7)) << 4);
}

// ---------------- K0: zero out + expert counters --------------------------------
__global__ void zero_out_kernel(float* __restrict__ out, int total4) {
    int i = blockIdx.x * blockDim.x + threadIdx.x;
    if (i < total4) *(float4*)(out + i * 4) = make_float4(0, 0, 0, 0);
    if (blockIdx.x == 0 && threadIdx.x < E_NUM) g_counts[threadIdx.x] = 0;
}

// ---------------- K1: router (fused x->fp16) -----------------------------------
__global__ void router_kernel(const float* __restrict__ x,
                              const float* __restrict__ gw, int T) {
    int warp = blockIdx.x * (blockDim.x >> 5) + (threadIdx.x >> 5);
    int lane = threadIdx.x & 31;
    if (warp >= T) return;
    const float* xr = x + (size_t)warp * D_DIM;
    __half* xh = g_xH + (size_t)warp * D_DIM;

    float acc[E_NUM];
#pragma unroll
    for (int e = 0; e < E_NUM; e++) acc[e] = 0.0f;
#pragma unroll
    for (int i = 0; i < D_DIM / 128; i++) {
        int d = i * 128 + lane * 4;
        float4 xv = *(const float4*)(xr + d);
        __half2 h0 = __floats2half2_rn(xv.x, xv.y);
        __half2 h1 = __floats2half2_rn(xv.z, xv.w);
        *(uint2*)(xh + d) = make_uint2(*(uint32_t*)&h0, *(uint32_t*)&h1);
#pragma unroll
        for (int e = 0; e < E_NUM; e++) {
            float4 gv = *(const float4*)(gw + e * D_DIM + d);
            acc[e] += xv.x * gv.x + xv.y * gv.y + xv.z * gv.z + xv.w * gv.w;
        }
    }
#pragma unroll
    for (int e = 0; e < E_NUM; e++) {
#pragma unroll
        for (int off = 16; off > 0; off >>= 1)
            acc[e] += __shfl_xor_sync(0xFFFFFFFFu, acc[e], off);
    }
    if (lane == 0) {
        int e0 = 0; float s0 = acc[0];
#pragma unroll
        for (int e = 1; e < E_NUM; e++) if (acc[e] > s0) { s0 = acc[e]; e0 = e; }
        int e1 = -1; float s1 = -3.4e38f;
#pragma unroll
        for (int e = 0; e < E_NUM; e++)
            if (e != e0 && acc[e] > s1) { s1 = acc[e]; e1 = e; }
        float x1 = __expf(s1 - s0);
        float inv = 1.0f / (1.0f + x1);
        int t = warp;
        g_probs[2 * t] = inv;
        g_probs[2 * t + 1] = x1 * inv;
        int j0 = atomicAdd(&g_counts[e0], 1);
        g_list[e0 * T_MAX + j0] = (t << 1);
        int j1 = atomicAdd(&g_counts[e1], 1);
        g_list[e1 * T_MAX + j1] = (t << 1) | 1;
    }
}

// ---------------- K2: build (inline scan, + per-row prob) ----------------------
__global__ void build_kernel() {
    __shared__ int s_exp, s_off, s_cnt;
    if (threadIdx.x == 0) {
        int off = 0, nt = 0, my_e = -1, my_off = 0, my_cnt = 0;
#pragma unroll
        for (int e = 0; e < E_NUM; e++) {
            int c = g_counts[e];
            int te = (c + BM - 1) / BM;
            if ((int)blockIdx.x >= nt && (int)blockIdx.x < nt + te) {
                my_e = e; my_off = off; my_cnt = c;
            }
            nt += te;
            off += te * BM;
        }
        g_tile_expert[blockIdx.x] = my_e;
        s_exp = my_e; s_off = my_off; s_cnt = my_cnt;
    }
    __syncthreads();
    int e = s_exp;
    int r = blockIdx.x * BM + threadIdx.x;
    if (e < 0) { g_gather[r] = -1; g_rowprob[r] = 0.0f; return; }
    int j = r - s_off;
    if (j < s_cnt) {
        int entry = g_list[e * T_MAX + j];
        g_gather[r] = entry >> 1;
        g_rowprob[r] = g_probs[entry];
    } else {
        g_gather[r] = -1;
        g_rowprob[r] = 0.0f;
    }
}

// ---------------- weight conversion -------------------------------------------
__global__ void conv_w_all_kernel(const float* __restrict__ w1,
                                  const float* __restrict__ w2,
                                  const float* __restrict__ w3, long n4) {
    long i = blockIdx.x * (long)blockDim.x + threadIdx.x;
    if (i >= 3 * n4) return;
    const float* src;
    __half* dst;
    long j;
    if (i < n4)           { src = w1; dst = g_w1H; j = i; }
    else if (i < 2 * n4)  { src = w2; dst = g_w2H; j = i - n4; }
    else                  { src = w3; dst = g_w3H; j = i - 2 * n4; }
    long eb = j * 4;
    float4 v = *(const float4*)(src + eb);
    __half2 h0 = __floats2half2_rn(v.x, v.y);
    __half2 h1 = __floats2half2_rn(v.z, v.w);
    *(uint2*)(dst + eb) = make_uint2(*(uint32_t*)&h0, *(uint32_t*)&h1);
}

// ---------------- K4: up GEMM — paired B-ldsm issue ------------------------------
__global__ void __launch_bounds__(512, 1) gemm_up_mma() {
    const int e = g_tile_expert[blockIdx.y];
    if (e < 0) return;
    extern __shared__ char raw[];
    char* dsm = (char*)(((uintptr_t)raw + 1023) & ~(uintptr_t)1023);
    __shared__ int sg[BM];
    const int tid = threadIdx.x;
    const int m0 = blockIdx.y * BM;
    const int bn0 = blockIdx.x * 128;
    if (tid < BM) sg[tid] = g_gather[m0 + tid];
    __syncthreads();
    const uint32_t sb = smem_u32(dsm);
    const int lane = tid & 31, wid = tid >> 5;
    const int wm = wid & 3, wn = wid >> 2;

    const char* asrc[2]; int asz[2]; int dA[2];
    const char* b1s[2];
    const size_t w2delta = (const char*)g_w2H - (const char*)g_w1H;
#pragma unroll
    for (int i = 0; i < 2; i++) {
        int idx = tid + i * 512;
        int r = idx >> 3, c = idx & 7;
        dA[i] = sw_off(r, c);
        int tok = sg[r];
        asrc[i] = (tok >= 0) ? (const char*)(g_xH + (size_t)tok * D_DIM + c * 8)
                             : (const char*)g_xH;
        asz[i] = (tok >= 0) ? 16 : 0;
        b1s[i] = (const char*)(g_w1H + ((size_t)e * H_DIM + bn0 + r) * D_DIM + c * 8);
    }

#define U_LOAD(KT) do {                                                         \
    const int _s = (KT) % NSTAGE;                                               \
    const uint32_t _b = sb + _s * STAGE_BYTES;                                  \
    const int _k = (KT) * (BKW * 2);                                            \
    _Pragma("unroll") for (int i = 0; i < 2; i++) {                             \
        cp16(_b + dA[i], asrc[i] + _k, asz[i]);                                 \
        cp16(_b + 16384 + dA[i], b1s[i] + _k, 16);                              \
        cp16(_b + 32768 + dA[i], b1s[i] + w2delta + _k, 16);                    \
    } } while (0)

    U_LOAD(0); CP_COMMIT;
    U_LOAD(1); CP_COMMIT;
    U_LOAD(2); CP_COMMIT;

    float cu[2][4][4], cv[2][4][4];
#pragma unroll
    for (int a = 0; a < 2; a++)
#pragma unroll
        for (int b = 0; b < 4; b++)
#pragma unroll
            for (int c = 0; c < 4; c++) { cu[a][b][c] = 0.0f; cv[a][b][c] = 0.0f; }

    const int ar0 = wm * 32 + (lane & 15);
    const int acs = (lane >> 4);

    for (int kt = 0; kt < UP_NK; kt++) {
        cp_wait<2>(); __syncthreads();
        if (kt + 3 < UP_NK) U_LOAD(kt + 3);
        CP_COMMIT;
        const uint32_t At  = sb + (kt % NSTAGE) * STAGE_BYTES;
        const uint32_t B1t = At + 16384;
        const uint32_t B2t = At + 32768;

        uint32_t afr[2][2][4];
#pragma unroll
        for (int mi = 0; mi < 2; mi++)
            ldsm4(afr[0][mi][0], afr[0][mi][1], afr[0][mi][2], afr[0][mi][3],
                  At + sw_off(ar0 + mi * 16, acs));
#pragma unroll
        for (int ks = 0; ks < 4; ks++) {
            const int cb = ks & 1, nb = cb ^ 1;
            if (ks < 3) {
#pragma unroll
                for (int mi = 0; mi < 2; mi++)
                    ldsm4(afr[nb][mi][0], afr[nb][mi][1], afr[nb][mi][2], afr[nb][mi][3],
                          At + sw_off(ar0 + mi * 16, (ks + 1) * 2 + acs));
            }
#pragma unroll
            for (int bj = 0; bj < 2; bj++) {
                int r = wn * 32 + bj * 16 + ((lane >> 4) << 3) + (lane & 7);
                int c = ks * 2 + ((lane >> 3) & 1);
                int off = sw_off(r, c);
                uint32_t q0, q1, q2, q3, p0, p1, p2, p3;
                ldsm4(q0, q1, q2, q3, B1t + off);   // both B loads issued
                ldsm4(p0, p1, p2, p3, B2t + off);   // back-to-back: latencies overlap
                { uint32_t b[2] = {q0, q1};
                  mma16816(cu[0][2 * bj], afr[cb][0], b);
                  mma16816(cu[1][2 * bj], afr[cb][1], b); }
                { uint32_t b[2] = {q2, q3};
                  mma16816(cu[0][2 * bj + 1], afr[cb][0], b);
                  mma16816(cu[1][2 * bj + 1], afr[cb][1], b); }
                { uint32_t b[2] = {p0, p1};
                  mma16816(cv[0][2 * bj], afr[cb][0], b);
                  mma16816(cv[1][2 * bj], afr[cb][1], b); }
                { uint32_t b[2] = {p2, p3};
                  mma16816(cv[0][2 * bj + 1], afr[cb][0], b);
                  mma16816(cv[1][2 * bj + 1], afr[cb][1], b); }
            }
        }
    }
#undef U_LOAD

#pragma unroll
    for (int mi = 0; mi < 2; mi++) {
#pragma unroll
        for (int nj = 0; nj < 4; nj++) {
            int r0 = m0 + wm * 32 + mi * 16 + (lane >> 2);
            int col = bn0 + wn * 32 + nj * 8 + (lane & 3) * 2;
#pragma unroll
            for (int h = 0; h < 2; h++) {
                int r = r0 + 8 * h;
                float f0 = silu_f(cu[mi][nj][2 * h])     * cv[mi][nj][2 * h];
                float f1 = silu_f(cu[mi][nj][2 * h + 1]) * cv[mi][nj][2 * h + 1];
                __half2 hh = __floats2half2_rn(f0, f1);
                *(__half2*)(g_hH + (size_t)r * H_DIM + col) = hh;
            }
        }
    }
}

// ---------------- K5: down GEMM — paired B-ldsm issue + fused combine -----------
__global__ void __launch_bounds__(512, 1) gemm_down_mma(float* __restrict__ out) {
    const int e = g_tile_expert[blockIdx.y];
    if (e < 0) return;
    extern __shared__ char raw[];
    char* dsm = (char*)(((uintptr_t)raw + 1023) & ~(uintptr_t)1023);
    const int tid = threadIdx.x;
    const int m0 = blockIdx.y * BM;
    const int bn0 = blockIdx.x * 256;
    const uint32_t sb = smem_u32(dsm);
    const int lane = tid & 31, wid = tid >> 5;
    const int wm = wid & 3, wn = wid >> 2;

    const char* asrc[2]; int dA[2];
    const char* bsrc[4]; int dB[4];
#pragma unroll
    for (int i = 0; i < 2; i++) {
        int idx = tid + i * 512;
        int r = idx >> 3, c = idx & 7;
        dA[i] = sw_off(r, c);
        asrc[i] = (const char*)(g_hH + (size_t)(m0 + r) * H_DIM + c * 8);
    }
#pragma unroll
    for (int i = 0; i < 4; i++) {
        int idx = tid + i * 512;
        int r = idx >> 3, c = idx & 7;
        dB[i] = sw_off(r, c);
        bsrc[i] = (const char*)(g_w3H + ((size_t)e * D_DIM + bn0 + r) * H_DIM + c * 8);
    }

#define D_LOAD(KT) do {                                                         \
    const int _s = (KT) % NSTAGE;                                               \
    const uint32_t _b = sb + _s * STAGE_BYTES;                                  \
    const long _k = (long)(KT) * (BKW * 2);                                     \
    _Pragma("unroll") for (int i = 0; i < 2; i++)                               \
        cp16(_b + dA[i], asrc[i] + _k, 16);                                     \
    _Pragma("unroll") for (int i = 0; i < 4; i++)                               \
        cp16(_b + 16384 + dB[i], bsrc[i] + _k, 16);                             \
    } while (0)

    D_LOAD(0); CP_COMMIT;
    D_LOAD(1); CP_COMMIT;
    D_LOAD(2); CP_COMMIT;

    float acc[2][8][4];
#pragma unroll
    for (int a = 0; a < 2; a++)
#pragma unroll
        for (int b = 0; b < 8; b++)
#pragma unroll
            for (int c = 0; c < 4; c++) acc[a][b][c] = 0.0f;

    const int ar0 = wm * 32 + (lane & 15);
    const int acs = (lane >> 4);

    for (int kt = 0; kt < DN_NK; kt++) {
        cp_wait<2>(); __syncthreads();
        if (kt + 3 < DN_NK) D_LOAD(kt + 3);
        CP_COMMIT;
        const uint32_t At = sb + (kt % NSTAGE) * STAGE_BYTES;
        const uint32_t Bt = At + 16384;

        uint32_t afr[2][2][4];
#pragma unroll
        for (int mi = 0; mi < 2; mi++)
            ldsm4(afr[0][mi][0], afr[0][mi][1], afr[0][mi][2], afr[0][mi][3],
                  At + sw_off(ar0 + mi * 16, acs));
#pragma unroll
        for (int ks = 0; ks < 4; ks++) {
            const int cb = ks & 1, nb = cb ^ 1;
            if (ks < 3) {
#pragma unroll
                for (int mi = 0; mi < 2; mi++)
                    ldsm4(afr[nb][mi][0], afr[nb][mi][1], afr[nb][mi][2], afr[nb][mi][3],
                          At + sw_off(ar0 + mi * 16, (ks + 1) * 2 + acs));
            }
#pragma unroll
            for (int bjp = 0; bjp < 2; bjp++) {      // bj pairs: 2 ldsm back-to-back
                const int bj0 = 2 * bjp, bj1 = bj0 + 1;
                int c = ks * 2 + ((lane >> 3) & 1);
                int rb = ((lane >> 4) << 3) + (lane & 7);
                uint32_t q0, q1, q2, q3, p0, p1, p2, p3;
                ldsm4(q0, q1, q2, q3, Bt + sw_off(wn * 64 + bj0 * 16 + rb, c));
                ldsm4(p0, p1, p2, p3, Bt + sw_off(wn * 64 + bj1 * 16 + rb, c));
                { uint32_t b[2] = {q0, q1};
                  mma16816(acc[0][2 * bj0], afr[cb][0], b);
                  mma16816(acc[1][2 * bj0], afr[cb][1], b); }
                { uint32_t b[2] = {q2, q3};
                  mma16816(acc[0][2 * bj0 + 1], afr[cb][0], b);
                  mma16816(acc[1][2 * bj0 + 1], afr[cb][1], b); }
                { uint32_t b[2] = {p0, p1};
                  mma16816(acc[0][2 * bj1], afr[cb][0], b);
                  mma16816(acc[1][2 * bj1], afr[cb][1], b); }
                { uint32_t b[2] = {p2, p3};
                  mma16816(acc[0][2 * bj1 + 1], afr[cb][0], b);
                  mma16816(acc[1][2 * bj1 + 1], afr[cb][1], b); }
            }
        }
    }
#undef D_LOAD

    // fused combine: out[tok] += p * acc
    int   tk[2][2];
    float pp[2][2];
#pragma unroll
    for (int mi = 0; mi < 2; mi++) {
        int r0 = m0 + wm * 32 + mi * 16 + (lane >> 2);
#pragma unroll
        for (int h = 0; h < 2; h++) {
            int r = r0 + 8 * h;
            tk[mi][h] = g_gather[r];
            pp[mi][h] = g_rowprob[r];
        }
    }
#pragma unroll
    for (int mi = 0; mi < 2; mi++) {
#pragma unroll
        for (int nj = 0; nj < 8; nj++) {
            int col = bn0 + wn * 64 + nj * 8 + (lane & 3) * 2;
            if (tk[mi][0] >= 0)
                red2(out + (size_t)tk[mi][0] * D_DIM + col,
                     pp[mi][0] * acc[mi][nj][0], pp[mi][0] * acc[mi][nj][1]);
            if (tk[mi][1] >= 0)
                red2(out + (size_t)tk[mi][1] * D_DIM + col,
                     pp[mi][1] * acc[mi][nj][2], pp[mi][1] * acc[mi][nj][3]);
        }
    }
}

// ---------------- launch ---------------------------------------------------------
extern "C" void kernel_launch(void* const* d_in, const int* in_sizes, int n_in,
                              void* d_out, int out_size) {
    const float* x  = (const float*)d_in[0];
    const float* gw = (const float*)d_in[1];
    const float* w1 = (const float*)d_in[2];
    const float* w2 = (const float*)d_in[3];
    const float* w3 = (const float*)d_in[4];
    float* out = (float*)d_out;

    int T = in_sizes[0] / D_DIM;
    if (T > T_MAX) T = T_MAX;
    int m_tiles = (2 * T) / BM + E_NUM;
    if (m_tiles > MAX_TILES) m_tiles = MAX_TILES;

    cudaFuncSetAttribute(gemm_up_mma,   cudaFuncAttributeMaxDynamicSharedMemorySize, GEMM_SMEM);
    cudaFuncSetAttribute(gemm_down_mma, cudaFuncAttributeMaxDynamicSharedMemorySize, GEMM_SMEM);

    long n4 = (long)E_NUM * H_DIM * D_DIM / 4;
    bool fork = (g_s1 != 0 && g_ef != 0 && g_ej != 0);

    if (fork) {
        cudaEventRecord(g_ef, 0);
        cudaStreamWaitEvent(g_s1, g_ef, 0);
        conv_w_all_kernel<<<(int)((3 * n4 + 255) / 256), 256, 0, g_s1>>>(w1, w2, w3, n4);
        cudaEventRecord(g_ej, g_s1);
    }

    int out4 = T * (D_DIM / 4);
    zero_out_kernel<<<(out4 + 255) / 256, 256>>>(out, out4);
    router_kernel<<<(T + 7) / 8, 256>>>(x, gw, T);
    build_kernel<<<m_tiles, BM>>>();

    if (fork) cudaStreamWaitEvent(0, g_ej, 0);
    else conv_w_all_kernel<<<(int)((3 * n4 + 255) / 256), 256>>>(w1, w2, w3, n4);

    gemm_up_mma<<<dim3(H_DIM / 128, m_tiles), 512, GEMM_SMEM>>>();
    gemm_down_mma<<<dim3(D_DIM / 256, m_tiles), 512, GEMM_SMEM>>>(out);
}